// round 2
// baseline (speedup 1.0000x reference)
#include <cuda_runtime.h>
#include <cuda_bf16.h>
#include <stdint.h>

// ---------------------------------------------------------------------------
// Constants
// ---------------------------------------------------------------------------
#define MRR_A 0.987f
#define MRR_R 0.99f

#define OUT_CH 256
#define IN_CH  128
#define HW     56
#define HWSQ   3136        // 56*56
#define KTOT   1152        // 128*9
#define PIXTOT 200704      // 64*3136

#define KC      64         // K elements per smem stage (64 bf16 = 128B rows)
#define NCHUNK  18         // 1152/64
#define MT      128        // pixel tile (M)
#define NT      128        // oc tile (N)

// smem offsets (bytes, relative to dynamic smem base)
#define OFF_AHI   0
#define OFF_ALO   16384
#define OFF_BHI   32768
#define OFF_BLO   49152
#define OFF_SCALE 65536
#define OFF_BIAS  (OFF_SCALE + 512)
#define SMEM_TOTAL (OFF_BIAS + 512)

// ---------------------------------------------------------------------------
// Device-global scratch (no allocations allowed)
// ---------------------------------------------------------------------------
__device__ __nv_bfloat16 g_w_hi[OUT_CH * KTOT];
__device__ __nv_bfloat16 g_w_lo[OUT_CH * KTOT];
__device__ float g_scale[OUT_CH];
__device__ float g_bias[OUT_CH];

// ---------------------------------------------------------------------------
// Helpers
// ---------------------------------------------------------------------------
__device__ __forceinline__ uint32_t smem_u32(const void* p) {
    uint32_t a;
    asm("{ .reg .u64 t; cvta.to.shared.u64 t, %1; cvt.u32.u64 %0, t; }" : "=r"(a) : "l"(p));
    return a;
}

__device__ __forceinline__ uint32_t sw128(uint32_t off) {
    return off ^ ((off >> 3) & 0x70);
}

__device__ __forceinline__ void ldsm4(uint32_t* r, uint32_t addr) {
    asm volatile("ldmatrix.sync.aligned.m8n8.x4.shared.b16 {%0,%1,%2,%3}, [%4];"
                 : "=r"(r[0]), "=r"(r[1]), "=r"(r[2]), "=r"(r[3]) : "r"(addr));
}

__device__ __forceinline__ void mma16816(float* d, const uint32_t* a, const uint32_t* b) {
    asm volatile(
        "mma.sync.aligned.m16n8k16.row.col.f32.bf16.bf16.f32 "
        "{%0,%1,%2,%3}, {%4,%5,%6,%7}, {%8,%9}, {%0,%1,%2,%3};"
        : "+f"(d[0]), "+f"(d[1]), "+f"(d[2]), "+f"(d[3])
        : "r"(a[0]), "r"(a[1]), "r"(a[2]), "r"(a[3]), "r"(b[0]), "r"(b[1]));
}

__device__ __forceinline__ uint32_t pack_bf16(__nv_bfloat16 lo, __nv_bfloat16 hi) {
    uint16_t l = __bfloat16_as_ushort(lo);
    uint16_t h = __bfloat16_as_ushort(hi);
    return (uint32_t)l | ((uint32_t)h << 16);
}

// ---------------------------------------------------------------------------
// Kernel 1: MRR phase -> bf16 hi/lo weights + folded BN scale/bias
// ---------------------------------------------------------------------------
__global__ void prep_kernel(const float* __restrict__ phase,
                            const float* __restrict__ gamma,
                            const float* __restrict__ beta,
                            const float* __restrict__ rmean,
                            const float* __restrict__ rvar) {
    int idx = blockIdx.x * 256 + threadIdx.x;
    if (idx < OUT_CH * KTOT) {
        int oc = idx / KTOT;
        int k  = idx - oc * KTOT;
        int gy = oc >> 3, i = oc & 7;
        int gx = k >> 3,  j = k & 7;
        float phi = phase[((gy * 144 + gx) * 8 + i) * 8 + j];
        float c = cosf(phi);
        float ar = MRR_A * MRR_R;
        float num = MRR_A * MRR_A - 2.0f * ar * c + MRR_R * MRR_R;
        float den = 1.0f - 2.0f * ar * c + ar * ar;
        float tr = num / den;
        __nv_bfloat16 hi = __float2bfloat16(tr);
        g_w_hi[idx] = hi;
        g_w_lo[idx] = __float2bfloat16(tr - __bfloat162float(hi));
    }
    if (idx < OUT_CH) {
        float inv = gamma[idx] * rsqrtf(rvar[idx] + 1e-5f);
        g_scale[idx] = inv;
        g_bias[idx]  = beta[idx] - rmean[idx] * inv;
    }
}

// ---------------------------------------------------------------------------
// Kernel 2: implicit-GEMM conv via mma.sync bf16x3 compensated
//   D[pixel(128), oc(128)] = sum_k im2col(x)[p,k] * W[oc,k]
// ---------------------------------------------------------------------------
__global__ void __launch_bounds__(256, 1)
conv_kernel(const float* __restrict__ x, float* __restrict__ out) {
    extern __shared__ char smem[];
    const uint32_t sb = smem_u32(smem);
    const int tid = threadIdx.x;
    const int wid = tid >> 5;
    const int lid = tid & 31;
    const int p0  = blockIdx.x * MT;   // pixel tile base
    const int oc0 = blockIdx.y * NT;   // oc tile base

    const int warpM = wid >> 2;        // 0..1 -> 64-pixel row band
    const int warpN = wid & 3;         // 0..3 -> 32-oc column band

    if (tid < NT) {
        ((float*)(smem + OFF_SCALE))[tid] = g_scale[oc0 + tid];
        ((float*)(smem + OFF_BIAS))[tid]  = g_bias[oc0 + tid];
    }

    // per-thread fixed pixel for A (im2col) loading
    const int pl    = tid & 127;
    const int khalf = tid >> 7;        // 0/1
    const int pg    = p0 + pl;
    const int nimg  = pg / HWSQ;
    const int rem   = pg - nimg * HWSQ;
    const int oh    = rem / HW;
    const int ow    = rem - oh * HW;
    const float* xb = x + (size_t)nimg * IN_CH * HWSQ;

    const uint32_t* whi32 = (const uint32_t*)g_w_hi;
    const uint32_t* wlo32 = (const uint32_t*)g_w_lo;

    float acc[4][4][4];
    #pragma unroll
    for (int f = 0; f < 4; ++f)
        #pragma unroll
        for (int g = 0; g < 4; ++g)
            #pragma unroll
            for (int e = 0; e < 4; ++e) acc[f][g][e] = 0.0f;

    // precompute ldmatrix lane offsets (relative, unswizzled parts)
    const int li = lid >> 3;           // matrix index 0..3
    const int lj = lid & 7;            // row within 8x8
    // A: row_off = (li&1)*8 + lj, k_off = (li>>1)*8
    const int a_row = warpM * 64 + (li & 1) * 8 + lj;
    const int a_kof = (li >> 1) * 8;
    // B: row = warpN*32 + (li>>1)*8 + lj (+16 for second x4), k_off = (li&1)*8
    const int b_row = warpN * 32 + (li >> 1) * 8 + lj;
    const int b_kof = (li & 1) * 8;

    for (int kc = 0; kc < NCHUNK; ++kc) {
        const int k0 = kc * KC;
        if (kc) __syncthreads();   // smem reuse safe: everyone done with mma reads

        // ---- A tiles: im2col gather, hi/lo split, k-pair packed stores ----
        #pragma unroll
        for (int it = 0; it < 16; ++it) {
            const int kk = khalf * 2 + it * 4;   // even
            float v0 = 0.0f, v1 = 0.0f;
            {
                const int k = k0 + kk;
                const int c  = k / 9;
                const int rs = k - c * 9;
                const int r  = rs / 3;
                const int s  = rs - r * 3;
                const int ih = oh + r - 1;
                const int iw = ow + s - 1;
                if ((unsigned)ih < (unsigned)HW && (unsigned)iw < (unsigned)HW)
                    v0 = __ldg(xb + c * HWSQ + ih * HW + iw);
            }
            {
                const int k = k0 + kk + 1;
                const int c  = k / 9;
                const int rs = k - c * 9;
                const int r  = rs / 3;
                const int s  = rs - r * 3;
                const int ih = oh + r - 1;
                const int iw = ow + s - 1;
                if ((unsigned)ih < (unsigned)HW && (unsigned)iw < (unsigned)HW)
                    v1 = __ldg(xb + c * HWSQ + ih * HW + iw);
            }
            __nv_bfloat16 h0 = __float2bfloat16(v0);
            __nv_bfloat16 l0 = __float2bfloat16(v0 - __bfloat162float(h0));
            __nv_bfloat16 h1 = __float2bfloat16(v1);
            __nv_bfloat16 l1 = __float2bfloat16(v1 - __bfloat162float(h1));
            uint32_t sw = sw128((uint32_t)(pl * 128 + kk * 2));
            *(uint32_t*)(smem + OFF_AHI + sw) = pack_bf16(h0, h1);
            *(uint32_t*)(smem + OFF_ALO + sw) = pack_bf16(l0, l1);
        }

        // ---- B tiles: weights hi/lo, u32 copies (conflict-free) -----------
        #pragma unroll
        for (int it = 0; it < 16; ++it) {
            int e   = it * 256 + tid;
            int row = e >> 5;        // oc row 0..127
            int cp  = e & 31;        // u32 column pair 0..31
            int gix = ((oc0 + row) * KTOT + k0) / 2 + cp;
            uint32_t sw = sw128((uint32_t)(row * 128 + cp * 4));
            *(uint32_t*)(smem + OFF_BHI + sw) = whi32[gix];
            *(uint32_t*)(smem + OFF_BLO + sw) = wlo32[gix];
        }

        __syncthreads();

        // ---- compute: 4 k16-steps, bf16x3 compensation --------------------
        #pragma unroll
        for (int ks = 0; ks < 4; ++ks) {
            uint32_t Ahi[4][4], Alo[4][4], Bhi[4][2], Blo[4][2];

            #pragma unroll
            for (int f = 0; f < 4; ++f) {
                uint32_t off = sw128((uint32_t)((a_row + f * 16) * 128 +
                                                (ks * 16 + a_kof) * 2));
                ldsm4(Ahi[f], sb + OFF_AHI + off);
                ldsm4(Alo[f], sb + OFF_ALO + off);
            }
            #pragma unroll
            for (int h = 0; h < 2; ++h) {
                uint32_t off = sw128((uint32_t)((b_row + h * 16) * 128 +
                                                (ks * 16 + b_kof) * 2));
                uint32_t t[4];
                ldsm4(t, sb + OFF_BHI + off);
                Bhi[h*2+0][0] = t[0]; Bhi[h*2+0][1] = t[1];
                Bhi[h*2+1][0] = t[2]; Bhi[h*2+1][1] = t[3];
                ldsm4(t, sb + OFF_BLO + off);
                Blo[h*2+0][0] = t[0]; Blo[h*2+0][1] = t[1];
                Blo[h*2+1][0] = t[2]; Blo[h*2+1][1] = t[3];
            }

            #pragma unroll
            for (int f = 0; f < 4; ++f)
                #pragma unroll
                for (int g = 0; g < 4; ++g) {
                    mma16816(acc[f][g], Ahi[f], Bhi[g]);
                    mma16816(acc[f][g], Ahi[f], Blo[g]);
                    mma16816(acc[f][g], Alo[f], Bhi[g]);
                }
        }
    }

    // ---- epilogue: BN + ReLU6 + stores ------------------------------------
    const float* ss = (const float*)(smem + OFF_SCALE);
    const float* bb = (const float*)(smem + OFF_BIAS);

    #pragma unroll
    for (int f = 0; f < 4; ++f) {
        int p1 = p0 + warpM * 64 + f * 16 + (lid >> 2);
        int p2 = p1 + 8;
        int n1 = p1 / HWSQ, r1 = p1 - n1 * HWSQ;
        int n2 = p2 / HWSQ, r2 = p2 - n2 * HWSQ;
        float* o1 = out + (size_t)n1 * OUT_CH * HWSQ + r1;
        float* o2 = out + (size_t)n2 * OUT_CH * HWSQ + r2;
        #pragma unroll
        for (int g = 0; g < 4; ++g) {
            int cl = warpN * 32 + g * 8 + (lid & 3) * 2;  // 0..127 within tile
            int ocA = oc0 + cl, ocB = ocA + 1;
            float sA = ss[cl], bA = bb[cl];
            float sB = ss[cl + 1], bB = bb[cl + 1];
            float v0 = fminf(fmaxf(acc[f][g][0] * sA + bA, 0.0f), 6.0f);
            float v1 = fminf(fmaxf(acc[f][g][1] * sB + bB, 0.0f), 6.0f);
            float v2 = fminf(fmaxf(acc[f][g][2] * sA + bA, 0.0f), 6.0f);
            float v3 = fminf(fmaxf(acc[f][g][3] * sB + bB, 0.0f), 6.0f);
            o1[(size_t)ocA * HWSQ] = v0;
            o1[(size_t)ocB * HWSQ] = v1;
            o2[(size_t)ocA * HWSQ] = v2;
            o2[(size_t)ocB * HWSQ] = v3;
        }
    }
}

// ---------------------------------------------------------------------------
// Launch
// ---------------------------------------------------------------------------
extern "C" void kernel_launch(void* const* d_in, const int* in_sizes, int n_in,
                              void* d_out, int out_size) {
    const float* x     = (const float*)d_in[0];
    const float* phase = (const float*)d_in[1];
    const float* gamma = (const float*)d_in[2];
    const float* beta  = (const float*)d_in[3];
    const float* rmean = (const float*)d_in[4];
    const float* rvar  = (const float*)d_in[5];
    float* out = (float*)d_out;

    cudaFuncSetAttribute(conv_kernel,
                         cudaFuncAttributeMaxDynamicSharedMemorySize, SMEM_TOTAL);

    prep_kernel<<<(OUT_CH * KTOT + 255) / 256, 256>>>(phase, gamma, beta, rmean, rvar);

    dim3 grid(PIXTOT / MT, OUT_CH / NT);   // (1568, 2)
    conv_kernel<<<grid, 256, SMEM_TOTAL>>>(x, out);
}

// round 3
// speedup vs baseline: 1.4239x; 1.4239x over previous
#include <cuda_runtime.h>
#include <cuda_bf16.h>
#include <stdint.h>

// ---------------------------------------------------------------------------
// Constants
// ---------------------------------------------------------------------------
#define MRR_A 0.987f
#define MRR_R 0.99f

#define OUT_CH 256
#define IN_CH  128
#define HW     56
#define HWP    58          // padded spatial
#define HWSQ   3136
#define KTOT   1152
#define PIXTOT 200704

#define KC      64
#define NCHUNK  18         // 9 (r,s) positions x 2 channel-halves
#define MT      128
#define NT      128
#define STAGES  3

// per-stage smem layout (bytes)
#define STG_BYTES 65536
#define SOFF_AHI  0
#define SOFF_ALO  16384
#define SOFF_BHI  32768
#define SOFF_BLO  49152
#define OFF_SCALE (STAGES * STG_BYTES)          // 196608
#define OFF_BIAS  (OFF_SCALE + 512)
#define SMEM_TOTAL (OFF_BIAS + 512)             // 197632

// ---------------------------------------------------------------------------
// Device-global scratch (zero-initialized -> halo stays zero forever)
// ---------------------------------------------------------------------------
__device__ __align__(256) __nv_bfloat16 g_x_hi[64 * HWP * HWP * IN_CH];
__device__ __align__(256) __nv_bfloat16 g_x_lo[64 * HWP * HWP * IN_CH];
__device__ __align__(256) __nv_bfloat16 g_w_hi[OUT_CH * KTOT];   // [oc][rs][c]
__device__ __align__(256) __nv_bfloat16 g_w_lo[OUT_CH * KTOT];
__device__ float g_scale[OUT_CH];
__device__ float g_bias[OUT_CH];

// ---------------------------------------------------------------------------
// Helpers
// ---------------------------------------------------------------------------
__device__ __forceinline__ uint32_t smem_u32(const void* p) {
    uint32_t a;
    asm("{ .reg .u64 t; cvta.to.shared.u64 t, %1; cvt.u32.u64 %0, t; }" : "=r"(a) : "l"(p));
    return a;
}
__device__ __forceinline__ uint32_t sw128(uint32_t off) {
    return off ^ ((off >> 3) & 0x70);
}
__device__ __forceinline__ void cp16(uint32_t dst, const __nv_bfloat16* src) {
    asm volatile("cp.async.cg.shared.global [%0], [%1], 16;"
                 :: "r"(dst), "l"(__cvta_generic_to_global(src)));
}
#define CP_COMMIT() asm volatile("cp.async.commit_group;" ::: "memory")
#define CP_WAIT1()  asm volatile("cp.async.wait_group 1;" ::: "memory")

__device__ __forceinline__ void ldsm4(uint32_t* r, uint32_t addr) {
    asm volatile("ldmatrix.sync.aligned.m8n8.x4.shared.b16 {%0,%1,%2,%3}, [%4];"
                 : "=r"(r[0]), "=r"(r[1]), "=r"(r[2]), "=r"(r[3]) : "r"(addr));
}
__device__ __forceinline__ void mma16816(float* d, const uint32_t* a, const uint32_t* b) {
    asm volatile(
        "mma.sync.aligned.m16n8k16.row.col.f32.bf16.bf16.f32 "
        "{%0,%1,%2,%3}, {%4,%5,%6,%7}, {%8,%9}, {%0,%1,%2,%3};"
        : "+f"(d[0]), "+f"(d[1]), "+f"(d[2]), "+f"(d[3])
        : "r"(a[0]), "r"(a[1]), "r"(a[2]), "r"(a[3]), "r"(b[0]), "r"(b[1]));
}

// ---------------------------------------------------------------------------
// Kernel 1: weights — MRR phase -> bf16 hi/lo in [oc][rs][c] order + BN fold
// ---------------------------------------------------------------------------
__global__ void prep_kernel(const float* __restrict__ phase,
                            const float* __restrict__ gamma,
                            const float* __restrict__ beta,
                            const float* __restrict__ rmean,
                            const float* __restrict__ rvar) {
    int idx = blockIdx.x * 256 + threadIdx.x;
    if (idx < OUT_CH * KTOT) {
        int oc  = idx / KTOT;
        int kp  = idx - oc * KTOT;     // rs*128 + c
        int rs  = kp >> 7;
        int c   = kp & 127;
        int korig = c * 9 + rs;        // original (c,r,s) K order used by the blocks
        int gy = oc >> 3, i = oc & 7;
        int gx = korig >> 3, j = korig & 7;
        float phi = phase[((gy * 144 + gx) * 8 + i) * 8 + j];
        float cc = cosf(phi);
        float ar = MRR_A * MRR_R;
        float num = MRR_A * MRR_A - 2.0f * ar * cc + MRR_R * MRR_R;
        float den = 1.0f - 2.0f * ar * cc + ar * ar;
        float tr = num / den;
        __nv_bfloat16 hi = __float2bfloat16(tr);
        g_w_hi[idx] = hi;
        g_w_lo[idx] = __float2bfloat16(tr - __bfloat162float(hi));
    }
    if (idx < OUT_CH) {
        float inv = gamma[idx] * rsqrtf(rvar[idx] + 1e-5f);
        g_scale[idx] = inv;
        g_bias[idx]  = beta[idx] - rmean[idx] * inv;
    }
}

// ---------------------------------------------------------------------------
// Kernel 2: x NCHW fp32 -> padded NHWC bf16 hi/lo (smem transpose)
// ---------------------------------------------------------------------------
__global__ void __launch_bounds__(256)
xprep_kernel(const float* __restrict__ x) {
    __shared__ float tile[IN_CH][HW + 1];
    const int n = blockIdx.x, h = blockIdx.y;
    const int tid = threadIdx.x;
    const float* xb = x + (size_t)n * IN_CH * HWSQ + h * HW;
    #pragma unroll 4
    for (int i = tid; i < IN_CH * HW; i += 256) {
        int c = i / HW, w = i - c * HW;
        tile[c][w] = xb[(size_t)c * HWSQ + w];
    }
    __syncthreads();
    const size_t obase = (((size_t)n * HWP + h + 1) * HWP + 1) * IN_CH;
    #pragma unroll 4
    for (int i = tid; i < HW * IN_CH; i += 256) {
        int w = i >> 7, c = i & 127;
        float v = tile[c][w];
        __nv_bfloat16 hi = __float2bfloat16(v);
        g_x_hi[obase + (size_t)w * IN_CH + c] = hi;
        g_x_lo[obase + (size_t)w * IN_CH + c] = __float2bfloat16(v - __bfloat162float(hi));
    }
}

// ---------------------------------------------------------------------------
// Kernel 3: implicit-GEMM conv, cp.async 3-stage pipeline, bf16x3 mma.sync
// ---------------------------------------------------------------------------
__global__ void __launch_bounds__(256, 1)
conv_kernel(float* __restrict__ out) {
    extern __shared__ char smem[];
    const uint32_t sb = smem_u32(smem);
    const int tid = threadIdx.x;
    const int wid = tid >> 5;
    const int lid = tid & 31;
    const int p0  = blockIdx.x * MT;
    const int oc0 = blockIdx.y * NT;

    const int warpM = wid >> 2;
    const int warpN = wid & 3;

    if (tid < NT) {
        ((float*)(smem + OFF_SCALE))[tid] = g_scale[oc0 + tid];
        ((float*)(smem + OFF_BIAS))[tid]  = g_bias[oc0 + tid];
    }

    // ---- per-thread load assignment: row = tid>>1 (pixel row & oc row) ----
    const int lrow = tid >> 1;
    const int segb = (tid & 1) * 4;            // 16B-segment start (of 8)
    const int pg   = p0 + lrow;
    const int nimg = pg / HWSQ;
    const int rem  = pg - nimg * HWSQ;
    const int oh   = rem / HW;
    const int ow   = rem - oh * HW;
    const __nv_bfloat16* xhi_n = g_x_hi + (size_t)nimg * (HWP * HWP * IN_CH);
    const __nv_bfloat16* xlo_n = g_x_lo + (size_t)nimg * (HWP * HWP * IN_CH);
    // swizzled smem dst offsets for the 4 segments (row fixed)
    uint32_t dsts[4];
    #pragma unroll
    for (int j = 0; j < 4; ++j)
        dsts[j] = sw128((uint32_t)(lrow * 128 + (segb + j) * 16));

    // issue loads of chunk kc into stage st
    auto issue_loads = [&](int kc, int st) {
        const int rs = kc >> 1, half = kc & 1;
        const int r = rs / 3, s = rs - r * 3;
        const size_t aoff = (((size_t)(oh + r) * HWP) + (ow + s)) * IN_CH
                            + half * 64 + segb * 8;
        const __nv_bfloat16* ahi = xhi_n + aoff;
        const __nv_bfloat16* alo = xlo_n + aoff;
        const size_t boff = ((size_t)(oc0 + lrow) * 9 + rs) * 128
                            + half * 64 + segb * 8;
        const __nv_bfloat16* bhi = g_w_hi + boff;
        const __nv_bfloat16* blo = g_w_lo + boff;
        const uint32_t s0 = sb + st * STG_BYTES;
        #pragma unroll
        for (int j = 0; j < 4; ++j) {
            cp16(s0 + SOFF_AHI + dsts[j], ahi + j * 8);
            cp16(s0 + SOFF_ALO + dsts[j], alo + j * 8);
            cp16(s0 + SOFF_BHI + dsts[j], bhi + j * 8);
            cp16(s0 + SOFF_BLO + dsts[j], blo + j * 8);
        }
    };

    float acc[4][4][4];
    #pragma unroll
    for (int f = 0; f < 4; ++f)
        #pragma unroll
        for (int g = 0; g < 4; ++g)
            #pragma unroll
            for (int e = 0; e < 4; ++e) acc[f][g][e] = 0.0f;

    // ldmatrix lane mapping
    const int li = lid >> 3;
    const int lj = lid & 7;
    const int a_row = warpM * 64 + (li & 1) * 8 + lj;
    const int a_kof = (li >> 1) * 8;
    const int b_row = warpN * 32 + (li >> 1) * 8 + lj;
    const int b_kof = (li & 1) * 8;

    // ---- pipeline prologue ----
    issue_loads(0, 0); CP_COMMIT();
    issue_loads(1, 1); CP_COMMIT();

    for (int kc = 0; kc < NCHUNK; ++kc) {
        CP_WAIT1();            // stage kc resident
        __syncthreads();       // all warps done computing stage kc-1

        const int kn = kc + (STAGES - 1);
        if (kn < NCHUNK) issue_loads(kn, kn % STAGES);
        CP_COMMIT();

        const uint32_t s0 = sb + (kc % STAGES) * STG_BYTES;
        #pragma unroll
        for (int ks = 0; ks < 4; ++ks) {
            uint32_t Ahi[4][4], Alo[4][4], Bhi[4][2], Blo[4][2];
            #pragma unroll
            for (int f = 0; f < 4; ++f) {
                uint32_t off = sw128((uint32_t)((a_row + f * 16) * 128 +
                                                (ks * 16 + a_kof) * 2));
                ldsm4(Ahi[f], s0 + SOFF_AHI + off);
                ldsm4(Alo[f], s0 + SOFF_ALO + off);
            }
            #pragma unroll
            for (int h = 0; h < 2; ++h) {
                uint32_t off = sw128((uint32_t)((b_row + h * 16) * 128 +
                                                (ks * 16 + b_kof) * 2));
                uint32_t t[4];
                ldsm4(t, s0 + SOFF_BHI + off);
                Bhi[h*2+0][0] = t[0]; Bhi[h*2+0][1] = t[1];
                Bhi[h*2+1][0] = t[2]; Bhi[h*2+1][1] = t[3];
                ldsm4(t, s0 + SOFF_BLO + off);
                Blo[h*2+0][0] = t[0]; Blo[h*2+0][1] = t[1];
                Blo[h*2+1][0] = t[2]; Blo[h*2+1][1] = t[3];
            }
            #pragma unroll
            for (int f = 0; f < 4; ++f)
                #pragma unroll
                for (int g = 0; g < 4; ++g) {
                    mma16816(acc[f][g], Ahi[f], Bhi[g]);
                    mma16816(acc[f][g], Ahi[f], Blo[g]);
                    mma16816(acc[f][g], Alo[f], Bhi[g]);
                }
        }
    }

    // ---- epilogue: BN + ReLU6 + stores ------------------------------------
    const float* ss = (const float*)(smem + OFF_SCALE);
    const float* bb = (const float*)(smem + OFF_BIAS);

    #pragma unroll
    for (int f = 0; f < 4; ++f) {
        int p1 = p0 + warpM * 64 + f * 16 + (lid >> 2);
        int p2 = p1 + 8;
        int n1 = p1 / HWSQ, r1 = p1 - n1 * HWSQ;
        int n2 = p2 / HWSQ, r2 = p2 - n2 * HWSQ;
        float* o1 = out + (size_t)n1 * OUT_CH * HWSQ + r1;
        float* o2 = out + (size_t)n2 * OUT_CH * HWSQ + r2;
        #pragma unroll
        for (int g = 0; g < 4; ++g) {
            int cl = warpN * 32 + g * 8 + (lid & 3) * 2;
            int ocA = oc0 + cl, ocB = ocA + 1;
            float sA = ss[cl], bA = bb[cl];
            float sB = ss[cl + 1], bB = bb[cl + 1];
            float v0 = fminf(fmaxf(acc[f][g][0] * sA + bA, 0.0f), 6.0f);
            float v1 = fminf(fmaxf(acc[f][g][1] * sB + bB, 0.0f), 6.0f);
            float v2 = fminf(fmaxf(acc[f][g][2] * sA + bA, 0.0f), 6.0f);
            float v3 = fminf(fmaxf(acc[f][g][3] * sB + bB, 0.0f), 6.0f);
            o1[(size_t)ocA * HWSQ] = v0;
            o1[(size_t)ocB * HWSQ] = v1;
            o2[(size_t)ocA * HWSQ] = v2;
            o2[(size_t)ocB * HWSQ] = v3;
        }
    }
}

// ---------------------------------------------------------------------------
// Launch
// ---------------------------------------------------------------------------
extern "C" void kernel_launch(void* const* d_in, const int* in_sizes, int n_in,
                              void* d_out, int out_size) {
    const float* x     = (const float*)d_in[0];
    const float* phase = (const float*)d_in[1];
    const float* gamma = (const float*)d_in[2];
    const float* beta  = (const float*)d_in[3];
    const float* rmean = (const float*)d_in[4];
    const float* rvar  = (const float*)d_in[5];
    float* out = (float*)d_out;

    cudaFuncSetAttribute(conv_kernel,
                         cudaFuncAttributeMaxDynamicSharedMemorySize, SMEM_TOTAL);

    prep_kernel<<<(OUT_CH * KTOT + 255) / 256, 256>>>(phase, gamma, beta, rmean, rvar);
    dim3 xg(64, HW);
    xprep_kernel<<<xg, 256>>>(x);

    dim3 grid(PIXTOT / MT, OUT_CH / NT);   // (1568, 2)
    conv_kernel<<<grid, 256, SMEM_TOTAL>>>(out);
}

// round 4
// speedup vs baseline: 1.6003x; 1.1239x over previous
#include <cuda_runtime.h>
#include <cuda_bf16.h>
#include <stdint.h>

// ---------------------------------------------------------------------------
// Constants
// ---------------------------------------------------------------------------
#define MRR_A 0.987f
#define MRR_R 0.99f

#define OUT_CH 256
#define IN_CH  128
#define HW     56
#define HWP    58          // padded spatial
#define HWSQ   3136
#define KTOT   1152
#define PIXTOT 200704

#define KC      64
#define NCHUNK  18         // 9 (r,s) positions x 2 channel-halves
#define MT      128
#define NT      128
#define STAGES  3
#define NTHREADS 512

// per-stage smem layout (bytes)
#define STG_BYTES 65536
#define SOFF_AHI  0
#define SOFF_ALO  16384
#define SOFF_BHI  32768
#define SOFF_BLO  49152
#define OFF_SCALE (STAGES * STG_BYTES)          // 196608
#define OFF_BIAS  (OFF_SCALE + 512)
#define SMEM_TOTAL (OFF_BIAS + 512)             // 197632

// ---------------------------------------------------------------------------
// Device-global scratch (zero-initialized -> halo stays zero forever)
// ---------------------------------------------------------------------------
__device__ __align__(256) __nv_bfloat16 g_x_hi[64 * HWP * HWP * IN_CH];
__device__ __align__(256) __nv_bfloat16 g_x_lo[64 * HWP * HWP * IN_CH];
__device__ __align__(256) __nv_bfloat16 g_w_hi[OUT_CH * KTOT];   // [oc][rs][c]
__device__ __align__(256) __nv_bfloat16 g_w_lo[OUT_CH * KTOT];
__device__ float g_scale[OUT_CH];
__device__ float g_bias[OUT_CH];

// ---------------------------------------------------------------------------
// Helpers
// ---------------------------------------------------------------------------
__device__ __forceinline__ uint32_t smem_u32(const void* p) {
    uint32_t a;
    asm("{ .reg .u64 t; cvta.to.shared.u64 t, %1; cvt.u32.u64 %0, t; }" : "=r"(a) : "l"(p));
    return a;
}
__device__ __forceinline__ uint32_t sw128(uint32_t off) {
    return off ^ ((off >> 3) & 0x70);
}
__device__ __forceinline__ void cp16(uint32_t dst, const __nv_bfloat16* src) {
    asm volatile("cp.async.cg.shared.global [%0], [%1], 16;"
                 :: "r"(dst), "l"(__cvta_generic_to_global(src)));
}
#define CP_COMMIT() asm volatile("cp.async.commit_group;" ::: "memory")
#define CP_WAIT1()  asm volatile("cp.async.wait_group 1;" ::: "memory")

__device__ __forceinline__ void ldsm4(uint32_t* r, uint32_t addr) {
    asm volatile("ldmatrix.sync.aligned.m8n8.x4.shared.b16 {%0,%1,%2,%3}, [%4];"
                 : "=r"(r[0]), "=r"(r[1]), "=r"(r[2]), "=r"(r[3]) : "r"(addr));
}
__device__ __forceinline__ void mma16816(float* d, const uint32_t* a, const uint32_t* b) {
    asm volatile(
        "mma.sync.aligned.m16n8k16.row.col.f32.bf16.bf16.f32 "
        "{%0,%1,%2,%3}, {%4,%5,%6,%7}, {%8,%9}, {%0,%1,%2,%3};"
        : "+f"(d[0]), "+f"(d[1]), "+f"(d[2]), "+f"(d[3])
        : "r"(a[0]), "r"(a[1]), "r"(a[2]), "r"(a[3]), "r"(b[0]), "r"(b[1]));
}

// ---------------------------------------------------------------------------
// Kernel 1: weights — MRR phase -> bf16 hi/lo in [oc][rs][c] order + BN fold
// ---------------------------------------------------------------------------
__global__ void prep_kernel(const float* __restrict__ phase,
                            const float* __restrict__ gamma,
                            const float* __restrict__ beta,
                            const float* __restrict__ rmean,
                            const float* __restrict__ rvar) {
    int idx = blockIdx.x * 256 + threadIdx.x;
    if (idx < OUT_CH * KTOT) {
        int oc  = idx / KTOT;
        int kp  = idx - oc * KTOT;     // rs*128 + c
        int rs  = kp >> 7;
        int c   = kp & 127;
        int korig = c * 9 + rs;        // original (c,r,s) K order used by the blocks
        int gy = oc >> 3, i = oc & 7;
        int gx = korig >> 3, j = korig & 7;
        float phi = phase[((gy * 144 + gx) * 8 + i) * 8 + j];
        float cc = cosf(phi);
        float ar = MRR_A * MRR_R;
        float num = MRR_A * MRR_A - 2.0f * ar * cc + MRR_R * MRR_R;
        float den = 1.0f - 2.0f * ar * cc + ar * ar;
        float tr = num / den;
        __nv_bfloat16 hi = __float2bfloat16(tr);
        g_w_hi[idx] = hi;
        g_w_lo[idx] = __float2bfloat16(tr - __bfloat162float(hi));
    }
    if (idx < OUT_CH) {
        float inv = gamma[idx] * rsqrtf(rvar[idx] + 1e-5f);
        g_scale[idx] = inv;
        g_bias[idx]  = beta[idx] - rmean[idx] * inv;
    }
}

// ---------------------------------------------------------------------------
// Kernel 2: x NCHW fp32 -> padded NHWC bf16 hi/lo (smem transpose)
// ---------------------------------------------------------------------------
__global__ void __launch_bounds__(256)
xprep_kernel(const float* __restrict__ x) {
    __shared__ float tile[IN_CH][HW + 1];
    const int n = blockIdx.x, h = blockIdx.y;
    const int tid = threadIdx.x;
    const float* xb = x + (size_t)n * IN_CH * HWSQ + h * HW;
    #pragma unroll 4
    for (int i = tid; i < IN_CH * HW; i += 256) {
        int c = i / HW, w = i - c * HW;
        tile[c][w] = xb[(size_t)c * HWSQ + w];
    }
    __syncthreads();
    const size_t obase = (((size_t)n * HWP + h + 1) * HWP + 1) * IN_CH;
    #pragma unroll 4
    for (int i = tid; i < HW * IN_CH; i += 256) {
        int w = i >> 7, c = i & 127;
        float v = tile[c][w];
        __nv_bfloat16 hi = __float2bfloat16(v);
        g_x_hi[obase + (size_t)w * IN_CH + c] = hi;
        g_x_lo[obase + (size_t)w * IN_CH + c] = __float2bfloat16(v - __bfloat162float(hi));
    }
}

// ---------------------------------------------------------------------------
// Kernel 3: implicit-GEMM conv, cp.async 3-stage pipeline, bf16x3 mma.sync
//   512 threads, warp grid 4x4, warp tile 32x32 (4 warps per SMSP)
// ---------------------------------------------------------------------------
__global__ void __launch_bounds__(NTHREADS, 1)
conv_kernel(float* __restrict__ out) {
    extern __shared__ char smem[];
    const uint32_t sb = smem_u32(smem);
    const int tid = threadIdx.x;
    const int wid = tid >> 5;
    const int lid = tid & 31;
    const int p0  = blockIdx.x * MT;
    const int oc0 = blockIdx.y * NT;

    const int warpM = wid >> 2;        // 0..3 -> 32-pixel band
    const int warpN = wid & 3;         // 0..3 -> 32-oc band

    if (tid < NT) {
        ((float*)(smem + OFF_SCALE))[tid] = g_scale[oc0 + tid];
        ((float*)(smem + OFF_BIAS))[tid]  = g_bias[oc0 + tid];
    }

    // ---- per-thread load assignment: 4 threads per row, 2 segs each -------
    const int lrow = tid >> 2;                 // 0..127 (pixel row & oc row)
    const int segb = (tid & 3) * 2;            // 16B-segment start (of 8)
    const int pg   = p0 + lrow;
    const int nimg = pg / HWSQ;
    const int rem  = pg - nimg * HWSQ;
    const int oh   = rem / HW;
    const int ow   = rem - oh * HW;
    const __nv_bfloat16* xhi_n = g_x_hi + (size_t)nimg * (HWP * HWP * IN_CH);
    const __nv_bfloat16* xlo_n = g_x_lo + (size_t)nimg * (HWP * HWP * IN_CH);
    uint32_t dsts[2];
    #pragma unroll
    for (int j = 0; j < 2; ++j)
        dsts[j] = sw128((uint32_t)(lrow * 128 + (segb + j) * 16));

    auto issue_loads = [&](int kc, int st) {
        const int rs = kc >> 1, half = kc & 1;
        const int r = rs / 3, s = rs - r * 3;
        const size_t aoff = (((size_t)(oh + r) * HWP) + (ow + s)) * IN_CH
                            + half * 64 + segb * 8;
        const __nv_bfloat16* ahi = xhi_n + aoff;
        const __nv_bfloat16* alo = xlo_n + aoff;
        const size_t boff = ((size_t)(oc0 + lrow) * 9 + rs) * 128
                            + half * 64 + segb * 8;
        const __nv_bfloat16* bhi = g_w_hi + boff;
        const __nv_bfloat16* blo = g_w_lo + boff;
        const uint32_t s0 = sb + st * STG_BYTES;
        #pragma unroll
        for (int j = 0; j < 2; ++j) {
            cp16(s0 + SOFF_AHI + dsts[j], ahi + j * 8);
            cp16(s0 + SOFF_ALO + dsts[j], alo + j * 8);
            cp16(s0 + SOFF_BHI + dsts[j], bhi + j * 8);
            cp16(s0 + SOFF_BLO + dsts[j], blo + j * 8);
        }
    };

    float acc[2][4][4];
    #pragma unroll
    for (int f = 0; f < 2; ++f)
        #pragma unroll
        for (int g = 0; g < 4; ++g)
            #pragma unroll
            for (int e = 0; e < 4; ++e) acc[f][g][e] = 0.0f;

    // ldmatrix lane mapping
    const int li = lid >> 3;
    const int lj = lid & 7;
    const int a_row = warpM * 32 + (li & 1) * 8 + lj;
    const int a_kof = (li >> 1) * 8;
    const int b_row = warpN * 32 + (li >> 1) * 8 + lj;
    const int b_kof = (li & 1) * 8;

    // ---- pipeline prologue ----
    issue_loads(0, 0); CP_COMMIT();
    issue_loads(1, 1); CP_COMMIT();

    for (int kc = 0; kc < NCHUNK; ++kc) {
        CP_WAIT1();            // stage kc resident
        __syncthreads();       // all warps done reading stage (kc-1)%3

        const int kn = kc + (STAGES - 1);
        if (kn < NCHUNK) issue_loads(kn, kn % STAGES);
        CP_COMMIT();

        const uint32_t s0 = sb + (kc % STAGES) * STG_BYTES;
        #pragma unroll
        for (int ks = 0; ks < 4; ++ks) {
            uint32_t Ahi[2][4], Alo[2][4], Bhi[4][2], Blo[4][2];
            #pragma unroll
            for (int f = 0; f < 2; ++f) {
                uint32_t off = sw128((uint32_t)((a_row + f * 16) * 128 +
                                                (ks * 16 + a_kof) * 2));
                ldsm4(Ahi[f], s0 + SOFF_AHI + off);
                ldsm4(Alo[f], s0 + SOFF_ALO + off);
            }
            #pragma unroll
            for (int h = 0; h < 2; ++h) {
                uint32_t off = sw128((uint32_t)((b_row + h * 16) * 128 +
                                                (ks * 16 + b_kof) * 2));
                uint32_t t[4];
                ldsm4(t, s0 + SOFF_BHI + off);
                Bhi[h*2+0][0] = t[0]; Bhi[h*2+0][1] = t[1];
                Bhi[h*2+1][0] = t[2]; Bhi[h*2+1][1] = t[3];
                ldsm4(t, s0 + SOFF_BLO + off);
                Blo[h*2+0][0] = t[0]; Blo[h*2+0][1] = t[1];
                Blo[h*2+1][0] = t[2]; Blo[h*2+1][1] = t[3];
            }
            #pragma unroll
            for (int f = 0; f < 2; ++f)
                #pragma unroll
                for (int g = 0; g < 4; ++g) {
                    mma16816(acc[f][g], Ahi[f], Bhi[g]);
                    mma16816(acc[f][g], Ahi[f], Blo[g]);
                    mma16816(acc[f][g], Alo[f], Bhi[g]);
                }
        }
    }

    // ---- epilogue: BN + ReLU6 + stores ------------------------------------
    const float* ss = (const float*)(smem + OFF_SCALE);
    const float* bb = (const float*)(smem + OFF_BIAS);

    #pragma unroll
    for (int f = 0; f < 2; ++f) {
        int p1 = p0 + warpM * 32 + f * 16 + (lid >> 2);
        int p2 = p1 + 8;
        int n1 = p1 / HWSQ, r1 = p1 - n1 * HWSQ;
        int n2 = p2 / HWSQ, r2 = p2 - n2 * HWSQ;
        float* o1 = out + (size_t)n1 * OUT_CH * HWSQ + r1;
        float* o2 = out + (size_t)n2 * OUT_CH * HWSQ + r2;
        #pragma unroll
        for (int g = 0; g < 4; ++g) {
            int cl = warpN * 32 + g * 8 + (lid & 3) * 2;
            int ocA = oc0 + cl, ocB = ocA + 1;
            float sA = ss[cl], bA = bb[cl];
            float sB = ss[cl + 1], bB = bb[cl + 1];
            float v0 = fminf(fmaxf(acc[f][g][0] * sA + bA, 0.0f), 6.0f);
            float v1 = fminf(fmaxf(acc[f][g][1] * sB + bB, 0.0f), 6.0f);
            float v2 = fminf(fmaxf(acc[f][g][2] * sA + bA, 0.0f), 6.0f);
            float v3 = fminf(fmaxf(acc[f][g][3] * sB + bB, 0.0f), 6.0f);
            o1[(size_t)ocA * HWSQ] = v0;
            o1[(size_t)ocB * HWSQ] = v1;
            o2[(size_t)ocA * HWSQ] = v2;
            o2[(size_t)ocB * HWSQ] = v3;
        }
    }
}

// ---------------------------------------------------------------------------
// Launch
// ---------------------------------------------------------------------------
extern "C" void kernel_launch(void* const* d_in, const int* in_sizes, int n_in,
                              void* d_out, int out_size) {
    const float* x     = (const float*)d_in[0];
    const float* phase = (const float*)d_in[1];
    const float* gamma = (const float*)d_in[2];
    const float* beta  = (const float*)d_in[3];
    const float* rmean = (const float*)d_in[4];
    const float* rvar  = (const float*)d_in[5];
    float* out = (float*)d_out;

    cudaFuncSetAttribute(conv_kernel,
                         cudaFuncAttributeMaxDynamicSharedMemorySize, SMEM_TOTAL);

    prep_kernel<<<(OUT_CH * KTOT + 255) / 256, 256>>>(phase, gamma, beta, rmean, rvar);
    dim3 xg(64, HW);
    xprep_kernel<<<xg, 256>>>(x);

    dim3 grid(PIXTOT / MT, OUT_CH / NT);   // (1568, 2)
    conv_kernel<<<grid, NTHREADS, SMEM_TOTAL>>>(out);
}